// round 14
// baseline (speedup 1.0000x reference)
#include <cuda_runtime.h>

#define HW 1024

// Scratch buffers
__device__ float g_qkv[8 * 192 * HW];        // [b][192][1024]; q pre-scaled by dkh^-0.5*log2e
__device__ float g_convp[2 * 8 * 64 * HW];   // [cs][b][64][1024] conv partial sums (no bias)
__device__ float g_pacc[4 * 8 * 64 * HW];    // [wq][b][64][1024] partial softmax-weighted V sums
__device__ float g_pssum[4 * 8 * 8 * HW];    // [wq][b][n][1024] partial exp sums

typedef unsigned long long u64;

__device__ __forceinline__ u64 fma2(u64 a, u64 b, u64 c) {
  u64 d; asm("fma.rn.f32x2 %0,%1,%2,%3;" : "=l"(d) : "l"(a), "l"(b), "l"(c)); return d;
}
__device__ __forceinline__ u64 add2(u64 a, u64 b) {
  u64 d; asm("add.rn.f32x2 %0,%1,%2;" : "=l"(d) : "l"(a), "l"(b)); return d;
}
__device__ __forceinline__ u64 pack2(float lo, float hi) {
  u64 d; asm("mov.b64 %0,{%1,%2};" : "=l"(d) : "f"(lo), "f"(hi)); return d;
}
__device__ __forceinline__ void unpack2(u64 v, float& lo, float& hi) {
  asm("mov.b64 {%0,%1},%2;" : "=f"(lo), "=f"(hi) : "l"(v));
}
__device__ __forceinline__ float ex2f(float x) {
  float y; asm("ex2.approx.ftz.f32 %0,%1;" : "=f"(y) : "f"(x)); return y;
}

// ---------------------------------------------------------------------------
// Fused prep.
// blocks [0,256): conv3x3 c-split partials, cs(2) x b(8) x og(16), 32 ch each.
// blocks [256,640): qkv 1x1 projection into g_qkv.
// 256 threads, <=48KB dynamic smem, 3 blocks/SM.
// ---------------------------------------------------------------------------
__global__ __launch_bounds__(256, 3) void prep_kernel(
    const float* __restrict__ x,
    const float* __restrict__ conv_w,
    const float* __restrict__ qkv_w, const float* __restrict__ qkv_b,
    float* __restrict__ convp, float* __restrict__ qkv_out) {
  extern __shared__ char smraw[];
  int blk = blockIdx.x;
  int t = threadIdx.x;

  if (blk < 256) {
    u64* wdup = (u64*)smraw;                 // [4 o][32 c][9] dup u64 (9216B)
    float* xs = (float*)(smraw + 9216);      // [8 cc][34][34] planar (36992B)
    int cs = blk >> 7;
    int rem = blk & 127;
    int b = rem >> 4, og = rem & 15;
    int cbase = cs * 32;

    for (int i = t; i < 1152; i += 256) {
      int o = i / 288, r2 = i - o * 288;
      float wv = conv_w[(og * 4 + o) * 576 + cbase * 9 + r2];
      wdup[i] = pack2(wv, wv);
    }
    for (int i = t; i < 9248; i += 256) xs[i] = 0.f;

    int xcol = t & 31, m0 = t >> 5;
    u64 acc[4][2];
#pragma unroll
    for (int o = 0; o < 4; o++) { acc[o][0] = 0ull; acc[o][1] = 0ull; }

    for (int chunk = 0; chunk < 4; chunk++) {
      __syncthreads();
#pragma unroll
      for (int cc = 0; cc < 8; cc++) {
        const float* xp = x + (b * 64 + cbase + chunk * 8 + cc) * HW;
#pragma unroll
        for (int rg = 0; rg < 4; rg++) {
          int row = rg * 8 + m0;
          xs[cc * 1156 + (row + 1) * 34 + xcol + 1] = xp[row * 32 + xcol];
        }
      }
      __syncthreads();

#pragma unroll
      for (int cc = 0; cc < 8; cc++) {
        const float* xc = xs + cc * 1156;
        int crel = chunk * 8 + cc;
        u64 pr[2][9];
#pragma unroll
        for (int pi = 0; pi < 2; pi++) {
          int m = m0 + pi * 8;
          const float* base = xc + (2 * m) * 34 + xcol;
#pragma unroll
          for (int kw = 0; kw < 3; kw++) {
            float s0 = base[kw], s1 = base[34 + kw];
            float s2 = base[68 + kw], s3 = base[102 + kw];
            pr[pi][0 + kw] = pack2(s0, s1);
            pr[pi][3 + kw] = pack2(s1, s2);
            pr[pi][6 + kw] = pack2(s2, s3);
          }
        }
        const u64* wc = wdup + crel * 9;
#pragma unroll
        for (int o = 0; o < 4; o++) {
          const u64* wo = wc + o * 288;
          u64 a0 = acc[o][0], a1 = acc[o][1];
#pragma unroll
          for (int k = 0; k < 9; k++) {
            u64 wk = wo[k];
            a0 = fma2(pr[0][k], wk, a0);
            a1 = fma2(pr[1][k], wk, a1);
          }
          acc[o][0] = a0; acc[o][1] = a1;
        }
      }
    }

    float* cpb = convp + (cs * 8 + b) * 64 * HW + og * 4 * HW;
#pragma unroll
    for (int o = 0; o < 4; o++) {
#pragma unroll
      for (int pi = 0; pi < 2; pi++) {
        int m = m0 + pi * 8;
        float lo, hi; unpack2(acc[o][pi], lo, hi);
        cpb[o * HW + (2 * m) * 32 + xcol] = lo;
        cpb[o * HW + (2 * m + 1) * 32 + xcol] = hi;
      }
    }
  } else {
    float* xs = (float*)smraw;               // [64][128] 32KB
    u64* ws2 = (u64*)(smraw + 32768);        // [64][32]  16KB
    int r = blk - 256;
    int b = r / 48;
    int rem = r - b * 48;
    int og = rem >> 3, pt = rem & 7;
    int p0 = pt * 128;

    for (int i = t; i < 64 * 128; i += 256) {
      int c = i >> 7, pp = i & 127;
      xs[i] = x[(b * 64 + c) * HW + p0 + pp];
    }
    for (int i = t; i < 64 * 32; i += 256) {
      int c = i >> 5, o = i & 31;
      float wv = qkv_w[(og * 32 + o) * 64 + c];
      ws2[i] = pack2(wv, wv);
    }
    __syncthreads();

    int oi = t >> 5, pi = t & 31;
    u64 acc2[4][2];
#pragma unroll
    for (int a = 0; a < 4; a++) { acc2[a][0] = 0ull; acc2[a][1] = 0ull; }

    for (int c0 = 0; c0 < 64; c0 += 4) {
      u64 xv[4][2], wv[4][4];
#pragma unroll
      for (int cc = 0; cc < 4; cc++) {
        xv[cc][0] = *(const u64*)(xs + (c0 + cc) * 128 + pi * 2);
        xv[cc][1] = *(const u64*)(xs + (c0 + cc) * 128 + 64 + pi * 2);
      }
#pragma unroll
      for (int cc = 0; cc < 4; cc++)
#pragma unroll
        for (int a = 0; a < 4; a++) wv[cc][a] = ws2[(c0 + cc) * 32 + oi * 4 + a];
#pragma unroll
      for (int cc = 0; cc < 4; cc++)
#pragma unroll
        for (int a = 0; a < 4; a++) {
          acc2[a][0] = fma2(wv[cc][a], xv[cc][0], acc2[a][0]);
          acc2[a][1] = fma2(wv[cc][a], xv[cc][1], acc2[a][1]);
        }
    }

#pragma unroll
    for (int a = 0; a < 4; a++) {
      int o = og * 32 + oi * 4 + a;
      float bb = qkv_b[o];
      float sc = (o < 64) ? (0.35355339059327373f * 1.4426950408889634f) : 1.f;
      float* ob = qkv_out + (b * 192 + o) * HW + p0;
#pragma unroll
      for (int k = 0; k < 2; k++) {
        float lo, hi; unpack2(acc2[a][k], lo, hi);
        *(float2*)(ob + 64 * k + pi * 2) = make_float2(sc * (lo + bb), sc * (hi + bb));
      }
    }
  }
}

// ---------------------------------------------------------------------------
// Attention v5 (unchanged from R12): j-pair f32x2, per-warp h2 phase stagger,
// rw table in registers. grid (64 bn, 4 rowg, 4 wq), block 128.
// ---------------------------------------------------------------------------
#define AT5_K    0                     // [8 d][256 jl] f32 = 8192
#define AT5_V    8192                  // 8192
#define AT5_RELW 16384                 // 504 u64 dup = 4032
#define AT5_RELH 20416                 // 4032
#define AT5_SMEM 24448

__global__ __launch_bounds__(128, 4) void attn_kernel(
    const float* __restrict__ qkv,
    const float* __restrict__ relw, const float* __restrict__ relh,
    float* __restrict__ pacc, float* __restrict__ pssum) {
  extern __shared__ char sm[];
  float* kpl = (float*)(sm + AT5_K);
  float* vpl = (float*)(sm + AT5_V);
  u64* relwd = (u64*)(sm + AT5_RELW);
  u64* relhd = (u64*)(sm + AT5_RELH);
  int t = threadIdx.x;
  int bn = blockIdx.x;
  int b = bn >> 3, n = bn & 7;
  int rowg = blockIdx.y;   // 0..3
  int wq = blockIdx.z;     // 0..3

  const float* qb = qkv + (b * 192 + n * 8) * HW;
  const float* kb = qkv + (b * 192 + 64 + n * 8) * HW;
  const float* vb = qkv + (b * 192 + 128 + n * 8) * HW;

  for (int e = t; e < 2048; e += 128) {
    int d = e >> 8, jl = e & 255;
    int j = (jl >> 3) * 32 + wq * 8 + (jl & 7);
    kpl[e] = kb[d * HW + j];
    vpl[e] = vb[d * HW + j];
  }
  for (int e = t; e < 504; e += 128) {
    float a = relw[e]; relwd[e] = pack2(a, a);
    float c = relh[e]; relhd[e] = pack2(c, c);
  }
  __syncthreads();

  int i0 = rowg * 256 + 2 * t;       // rows i0, i0+1 (same h1; w1 <= 30)
  int h1 = i0 >> 5, w1 = i0 & 31;
  int wid = t >> 5;                  // warp id 0..3 -> h2 phase offset

  u64 q2[2][8];
#pragma unroll
  for (int d = 0; d < 8; d++) {
    float2 qv = *(const float2*)(qb + d * HW + i0);
    q2[0][d] = pack2(qv.x, qv.x);
    q2[1][d] = pack2(qv.y, qv.y);
  }

  u64 myrw[8];
#pragma unroll
  for (int r = 0; r < 2; r++) {
#pragma unroll
    for (int p = 0; p < 4; p++) {
      int m0 = wq * 8 + 2 * p - (w1 + r) + 31;
      u64 z0 = 0ull, z1 = 0ull;
#pragma unroll
      for (int d = 0; d < 8; d++) {
        z0 = fma2(q2[r][d], relwd[m0 * 8 + d], z0);
        z1 = fma2(q2[r][d], relwd[(m0 + 1) * 8 + d], z1);
      }
      float alo, ahi, blo, bhi;
      unpack2(z0, alo, ahi); unpack2(z1, blo, bhi);
      myrw[r * 4 + p] = pack2(alo, blo);
    }
  }

  u64 acc2[2][8];
  u64 ssum2[2] = {0ull, 0ull};
#pragma unroll
  for (int d = 0; d < 8; d++) { acc2[0][d] = 0ull; acc2[1][d] = 0ull; }

#pragma unroll 1
  for (int hh = 0; hh < 32; hh++) {
    int h2 = (hh + wid * 8) & 31;     // per-warp phase stagger
    const u64* rhp = relhd + (h2 - h1 + 31) * 8;
    u64 rh0 = 0ull, rh1 = 0ull;
#pragma unroll
    for (int d = 0; d < 8; d++) {
      u64 rv = rhp[d];
      rh0 = fma2(q2[0][d], rv, rh0);
      rh1 = fma2(q2[1][d], rv, rh1);
    }

    u64 s[8];
#pragma unroll
    for (int p = 0; p < 4; p++) {
      s[p] = add2(myrw[p], rh0);
      s[4 + p] = add2(myrw[4 + p], rh1);
    }
    int base = h2 * 8;
#pragma unroll
    for (int d = 0; d < 8; d++) {
      ulonglong2 kkA = *(const ulonglong2*)(kpl + d * 256 + base);
      ulonglong2 kkB = *(const ulonglong2*)(kpl + d * 256 + base + 4);
      u64 qa = q2[0][d], qb2 = q2[1][d];
      s[0] = fma2(qa, kkA.x, s[0]); s[1] = fma2(qa, kkA.y, s[1]);
      s[2] = fma2(qa, kkB.x, s[2]); s[3] = fma2(qa, kkB.y, s[3]);
      s[4] = fma2(qb2, kkA.x, s[4]); s[5] = fma2(qb2, kkA.y, s[5]);
      s[6] = fma2(qb2, kkB.x, s[6]); s[7] = fma2(qb2, kkB.y, s[7]);
    }

    u64 pexp[8];
#pragma unroll
    for (int k = 0; k < 8; k++) {
      float lo, hi; unpack2(s[k], lo, hi);
      pexp[k] = pack2(ex2f(lo), ex2f(hi));
    }
    ssum2[0] = add2(ssum2[0], add2(add2(pexp[0], pexp[1]), add2(pexp[2], pexp[3])));
    ssum2[1] = add2(ssum2[1], add2(add2(pexp[4], pexp[5]), add2(pexp[6], pexp[7])));

#pragma unroll
    for (int d = 0; d < 8; d++) {
      ulonglong2 vvA = *(const ulonglong2*)(vpl + d * 256 + base);
      ulonglong2 vvB = *(const ulonglong2*)(vpl + d * 256 + base + 4);
      u64 a0 = acc2[0][d], a1 = acc2[1][d];
      a0 = fma2(pexp[0], vvA.x, a0); a0 = fma2(pexp[1], vvA.y, a0);
      a0 = fma2(pexp[2], vvB.x, a0); a0 = fma2(pexp[3], vvB.y, a0);
      a1 = fma2(pexp[4], vvA.x, a1); a1 = fma2(pexp[5], vvA.y, a1);
      a1 = fma2(pexp[6], vvB.x, a1); a1 = fma2(pexp[7], vvB.y, a1);
      acc2[0][d] = a0; acc2[1][d] = a1;
    }
  }

  float s0lo, s0hi, s1lo, s1hi;
  unpack2(ssum2[0], s0lo, s0hi);
  unpack2(ssum2[1], s1lo, s1hi);
  *(float2*)(pssum + ((wq * 8 + b) * 8 + n) * HW + i0) =
      make_float2(s0lo + s0hi, s1lo + s1hi);
  float* ab = pacc + ((wq * 8 + b) * 64 + n * 8) * HW + i0;
#pragma unroll
  for (int d = 0; d < 8; d++) {
    float a0, a1, b0, b1;
    unpack2(acc2[0][d], a0, a1);
    unpack2(acc2[1][d], b0, b1);
    *(float2*)(ab + d * HW) = make_float2(a0 + a1, b0 + b1);
  }
}

// ---------------------------------------------------------------------------
// Output projection v2: 64-pos tiles -> grid (8 b, 2 og, 16 pt) = 256 blocks
// for 2x memory-level parallelism. Merges 4 attn partials + softmax division
// + GEMM (ch 64..127); og==0 blocks merge the 2 conv partials (ch 0..63).
// ---------------------------------------------------------------------------
__global__ __launch_bounds__(256) void proj_kernel(
    const float* __restrict__ pacc, const float* __restrict__ pssum,
    const float* __restrict__ convp, const float* __restrict__ conv_b,
    const float* __restrict__ w, const float* __restrict__ bias,
    float* __restrict__ out) {
  extern __shared__ char smraw[];
  float* invs = (float*)smraw;                     // [8][64] 2KB
  float* xs = (float*)(smraw + 2048);              // [64][64] 16KB
  u64* ws2 = (u64*)(smraw + 2048 + 16384);         // [64][32] 16KB
  int b = blockIdx.x, og = blockIdx.y, pt = blockIdx.z;
  int t = threadIdx.x;
  int p0 = pt * 64;

  for (int i = t; i < 512; i += 256) {
    int n = i >> 6, pp = i & 63;
    int idx = (b * 8 + n) * HW + p0 + pp;
    float s = pssum[idx] + pssum[idx + 64 * HW] +
              pssum[idx + 128 * HW] + pssum[idx + 192 * HW];
    invs[i] = 1.f / s;
  }
  for (int i = t; i < 64 * 32; i += 256) {
    int c = i >> 5, o = i & 31;
    float wv = w[(og * 32 + o) * 64 + c];
    ws2[i] = pack2(wv, wv);
  }
  __syncthreads();
  for (int i = t; i < 64 * 64; i += 256) {
    int c = i >> 6, pp = i & 63;
    int idx = (b * 64 + c) * HW + p0 + pp;
    float s = pacc[idx] + pacc[idx + 512 * HW] +
              pacc[idx + 1024 * HW] + pacc[idx + 1536 * HW];
    xs[i] = s * invs[(c >> 3) * 64 + pp];
  }
  __syncthreads();

  int oi = t >> 5, pi = t & 31;
  u64 acc2[4];
#pragma unroll
  for (int a = 0; a < 4; a++) acc2[a] = 0ull;

  for (int c0 = 0; c0 < 64; c0 += 4) {
    u64 xv[4], wv[4][4];
#pragma unroll
    for (int cc = 0; cc < 4; cc++)
      xv[cc] = *(const u64*)(xs + (c0 + cc) * 64 + pi * 2);
#pragma unroll
    for (int cc = 0; cc < 4; cc++)
#pragma unroll
      for (int a = 0; a < 4; a++) wv[cc][a] = ws2[(c0 + cc) * 32 + oi * 4 + a];
#pragma unroll
    for (int cc = 0; cc < 4; cc++)
#pragma unroll
      for (int a = 0; a < 4; a++)
        acc2[a] = fma2(wv[cc][a], xv[cc], acc2[a]);
  }

#pragma unroll
  for (int a = 0; a < 4; a++) {
    int o = og * 32 + oi * 4 + a;
    float bb = bias[o];
    float lo, hi; unpack2(acc2[a], lo, hi);
    *(float2*)(out + (b * 128 + 64 + o) * HW + p0 + pi * 2) =
        make_float2(lo + bb, hi + bb);
  }

  if (og == 0) {
    for (int i = t; i < 64 * 64; i += 256) {
      int oc = i >> 6, pp = i & 63;
      int idx = (b * 64 + oc) * HW + p0 + pp;
      float s = convp[idx] + convp[idx + 512 * HW];
      out[(b * 128 + oc) * HW + p0 + pp] = s + conv_b[oc];
    }
  }
}

// ---------------------------------------------------------------------------
extern "C" void kernel_launch(void* const* d_in, const int* in_sizes, int n_in,
                              void* d_out, int out_size) {
  (void)in_sizes; (void)n_in; (void)out_size;
  const float* x      = (const float*)d_in[0];
  const float* conv_w = (const float*)d_in[1];
  const float* conv_b = (const float*)d_in[2];
  const float* qkv_w  = (const float*)d_in[3];
  const float* qkv_b  = (const float*)d_in[4];
  const float* attn_w = (const float*)d_in[5];
  const float* attn_b = (const float*)d_in[6];
  const float* relw   = (const float*)d_in[7];
  const float* relh   = (const float*)d_in[8];
  float* out = (float*)d_out;

  float *qkv_s = nullptr, *convp = nullptr, *pacc = nullptr, *pssum = nullptr;
  cudaGetSymbolAddress((void**)&qkv_s, g_qkv);
  cudaGetSymbolAddress((void**)&convp, g_convp);
  cudaGetSymbolAddress((void**)&pacc, g_pacc);
  cudaGetSymbolAddress((void**)&pssum, g_pssum);

  const int PREP_SMEM = 49152;
  const int PROJ_SMEM = 2048 + 16384 + 16384;
  cudaFuncSetAttribute(prep_kernel, cudaFuncAttributeMaxDynamicSharedMemorySize, PREP_SMEM);
  cudaFuncSetAttribute(attn_kernel, cudaFuncAttributeMaxDynamicSharedMemorySize, AT5_SMEM);
  cudaFuncSetAttribute(proj_kernel, cudaFuncAttributeMaxDynamicSharedMemorySize, PROJ_SMEM);

  prep_kernel<<<640, 256, PREP_SMEM>>>(x, conv_w, qkv_w, qkv_b, convp, qkv_s);
  attn_kernel<<<dim3(64, 4, 4), 128, AT5_SMEM>>>(qkv_s, relw, relh, pacc, pssum);
  proj_kernel<<<dim3(8, 2, 16), 256, PROJ_SMEM>>>(pacc, pssum, convp, conv_b,
                                                  attn_w, attn_b, out);
}

// round 16
// speedup vs baseline: 1.7564x; 1.7564x over previous
#include <cuda_runtime.h>

#define HW 1024

// Scratch buffers
__device__ float g_qkv[8 * 192 * HW];        // [b][192][1024]; q pre-scaled by dkh^-0.5*log2e
__device__ float g_convp[4 * 8 * 64 * HW];   // [cs][b][64][1024] conv partial sums (no bias)
__device__ float g_pacc[4 * 8 * 64 * HW];    // [wq][b][64][1024] partial softmax-weighted V sums
__device__ float g_pssum[4 * 8 * 8 * HW];    // [wq][b][n][1024] partial exp sums

typedef unsigned long long u64;

__device__ __forceinline__ u64 fma2(u64 a, u64 b, u64 c) {
  u64 d; asm("fma.rn.f32x2 %0,%1,%2,%3;" : "=l"(d) : "l"(a), "l"(b), "l"(c)); return d;
}
__device__ __forceinline__ u64 add2(u64 a, u64 b) {
  u64 d; asm("add.rn.f32x2 %0,%1,%2;" : "=l"(d) : "l"(a), "l"(b)); return d;
}
__device__ __forceinline__ u64 pack2(float lo, float hi) {
  u64 d; asm("mov.b64 %0,{%1,%2};" : "=l"(d) : "f"(lo), "f"(hi)); return d;
}
__device__ __forceinline__ void unpack2(u64 v, float& lo, float& hi) {
  asm("mov.b64 {%0,%1},%2;" : "=f"(lo), "=f"(hi) : "l"(v));
}
__device__ __forceinline__ float ex2f(float x) {
  float y; asm("ex2.approx.ftz.f32 %0,%1;" : "=f"(y) : "f"(x)); return y;
}

// ---------------------------------------------------------------------------
// Fused prep (R12 config: 512 conv blocks of 16ch + 384 qkv blocks).
// ---------------------------------------------------------------------------
__global__ __launch_bounds__(256, 3) void prep_kernel(
    const float* __restrict__ x,
    const float* __restrict__ conv_w,
    const float* __restrict__ qkv_w, const float* __restrict__ qkv_b,
    float* __restrict__ convp, float* __restrict__ qkv_out) {
  extern __shared__ char smraw[];
  int blk = blockIdx.x;
  int t = threadIdx.x;

  if (blk < 512) {
    u64* wdup = (u64*)smraw;                 // [4 o][16 c][9] dup u64
    float* xs = (float*)(smraw + 4608);      // [8 cc][34][34] planar
    int cs = blk >> 7;
    int rem = blk & 127;
    int b = rem >> 4, og = rem & 15;
    int cbase = cs * 16;

    for (int i = t; i < 576; i += 256) {
      int o = i / 144, r2 = i - o * 144;
      float wv = conv_w[(og * 4 + o) * 576 + cbase * 9 + r2];
      wdup[i] = pack2(wv, wv);
    }
    for (int i = t; i < 9248; i += 256) xs[i] = 0.f;

    int xcol = t & 31, m0 = t >> 5;
    u64 acc[4][2];
#pragma unroll
    for (int o = 0; o < 4; o++) { acc[o][0] = 0ull; acc[o][1] = 0ull; }

    for (int chunk = 0; chunk < 2; chunk++) {
      __syncthreads();
#pragma unroll
      for (int cc = 0; cc < 8; cc++) {
        const float* xp = x + (b * 64 + cbase + chunk * 8 + cc) * HW;
#pragma unroll
        for (int rg = 0; rg < 4; rg++) {
          int row = rg * 8 + m0;
          xs[cc * 1156 + (row + 1) * 34 + xcol + 1] = xp[row * 32 + xcol];
        }
      }
      __syncthreads();

#pragma unroll
      for (int cc = 0; cc < 8; cc++) {
        const float* xc = xs + cc * 1156;
        int crel = chunk * 8 + cc;
        u64 pr[2][9];
#pragma unroll
        for (int pi = 0; pi < 2; pi++) {
          int m = m0 + pi * 8;
          const float* base = xc + (2 * m) * 34 + xcol;
#pragma unroll
          for (int kw = 0; kw < 3; kw++) {
            float s0 = base[kw], s1 = base[34 + kw];
            float s2 = base[68 + kw], s3 = base[102 + kw];
            pr[pi][0 + kw] = pack2(s0, s1);
            pr[pi][3 + kw] = pack2(s1, s2);
            pr[pi][6 + kw] = pack2(s2, s3);
          }
        }
        const u64* wc = wdup + crel * 9;
#pragma unroll
        for (int o = 0; o < 4; o++) {
          const u64* wo = wc + o * 144;
          u64 a0 = acc[o][0], a1 = acc[o][1];
#pragma unroll
          for (int k = 0; k < 9; k++) {
            u64 wk = wo[k];
            a0 = fma2(pr[0][k], wk, a0);
            a1 = fma2(pr[1][k], wk, a1);
          }
          acc[o][0] = a0; acc[o][1] = a1;
        }
      }
    }

    float* cpb = convp + (cs * 8 + b) * 64 * HW + og * 4 * HW;
#pragma unroll
    for (int o = 0; o < 4; o++) {
#pragma unroll
      for (int pi = 0; pi < 2; pi++) {
        int m = m0 + pi * 8;
        float lo, hi; unpack2(acc[o][pi], lo, hi);
        cpb[o * HW + (2 * m) * 32 + xcol] = lo;
        cpb[o * HW + (2 * m + 1) * 32 + xcol] = hi;
      }
    }
  } else {
    float* xs = (float*)smraw;               // [64][128] 32KB
    u64* ws2 = (u64*)(smraw + 32768);        // [64][32]  16KB
    int r = blk - 512;
    int b = r / 48;
    int rem = r - b * 48;
    int og = rem >> 3, pt = rem & 7;
    int p0 = pt * 128;

    // float4 staging
    for (int i = t; i < 2048; i += 256) {
      int c = i >> 5, pp4 = i & 31;
      *(float4*)&xs[c * 128 + pp4 * 4] =
          *(const float4*)&x[(b * 64 + c) * HW + p0 + pp4 * 4];
    }
    for (int i = t; i < 64 * 32; i += 256) {
      int c = i >> 5, o = i & 31;
      float wv = qkv_w[(og * 32 + o) * 64 + c];
      ws2[i] = pack2(wv, wv);
    }
    __syncthreads();

    int oi = t >> 5, pi = t & 31;
    u64 acc2[4][2];
#pragma unroll
    for (int a = 0; a < 4; a++) { acc2[a][0] = 0ull; acc2[a][1] = 0ull; }

    for (int c0 = 0; c0 < 64; c0 += 4) {
      u64 xv[4][2], wv[4][4];
#pragma unroll
      for (int cc = 0; cc < 4; cc++) {
        xv[cc][0] = *(const u64*)(xs + (c0 + cc) * 128 + pi * 2);
        xv[cc][1] = *(const u64*)(xs + (c0 + cc) * 128 + 64 + pi * 2);
      }
#pragma unroll
      for (int cc = 0; cc < 4; cc++)
#pragma unroll
        for (int a = 0; a < 4; a++) wv[cc][a] = ws2[(c0 + cc) * 32 + oi * 4 + a];
#pragma unroll
      for (int cc = 0; cc < 4; cc++)
#pragma unroll
        for (int a = 0; a < 4; a++) {
          acc2[a][0] = fma2(wv[cc][a], xv[cc][0], acc2[a][0]);
          acc2[a][1] = fma2(wv[cc][a], xv[cc][1], acc2[a][1]);
        }
    }

#pragma unroll
    for (int a = 0; a < 4; a++) {
      int o = og * 32 + oi * 4 + a;
      float bb = qkv_b[o];
      float sc = (o < 64) ? (0.35355339059327373f * 1.4426950408889634f) : 1.f;
      float* ob = qkv_out + (b * 192 + o) * HW + p0;
#pragma unroll
      for (int k = 0; k < 2; k++) {
        float lo, hi; unpack2(acc2[a][k], lo, hi);
        *(float2*)(ob + 64 * k + pi * 2) = make_float2(sc * (lo + bb), sc * (hi + bb));
      }
    }
  }
}

// ---------------------------------------------------------------------------
// Attention v5 (unchanged from R12): j-pair f32x2, per-warp h2 phase stagger,
// rw table in registers. grid (64 bn, 4 rowg, 4 wq), block 128.
// ---------------------------------------------------------------------------
#define AT5_K    0                     // [8 d][256 jl] f32 = 8192
#define AT5_V    8192                  // 8192
#define AT5_RELW 16384                 // 504 u64 dup = 4032
#define AT5_RELH 20416                 // 4032
#define AT5_SMEM 24448

__global__ __launch_bounds__(128, 4) void attn_kernel(
    const float* __restrict__ qkv,
    const float* __restrict__ relw, const float* __restrict__ relh,
    float* __restrict__ pacc, float* __restrict__ pssum) {
  extern __shared__ char sm[];
  float* kpl = (float*)(sm + AT5_K);
  float* vpl = (float*)(sm + AT5_V);
  u64* relwd = (u64*)(sm + AT5_RELW);
  u64* relhd = (u64*)(sm + AT5_RELH);
  int t = threadIdx.x;
  int bn = blockIdx.x;
  int b = bn >> 3, n = bn & 7;
  int rowg = blockIdx.y;   // 0..3
  int wq = blockIdx.z;     // 0..3

  const float* qb = qkv + (b * 192 + n * 8) * HW;
  const float* kb = qkv + (b * 192 + 64 + n * 8) * HW;
  const float* vb = qkv + (b * 192 + 128 + n * 8) * HW;

  for (int e = t; e < 2048; e += 128) {
    int d = e >> 8, jl = e & 255;
    int j = (jl >> 3) * 32 + wq * 8 + (jl & 7);
    kpl[e] = kb[d * HW + j];
    vpl[e] = vb[d * HW + j];
  }
  for (int e = t; e < 504; e += 128) {
    float a = relw[e]; relwd[e] = pack2(a, a);
    float c = relh[e]; relhd[e] = pack2(c, c);
  }
  __syncthreads();

  int i0 = rowg * 256 + 2 * t;       // rows i0, i0+1 (same h1; w1 <= 30)
  int h1 = i0 >> 5, w1 = i0 & 31;
  int wid = t >> 5;                  // warp id 0..3 -> h2 phase offset

  u64 q2[2][8];
#pragma unroll
  for (int d = 0; d < 8; d++) {
    float2 qv = *(const float2*)(qb + d * HW + i0);
    q2[0][d] = pack2(qv.x, qv.x);
    q2[1][d] = pack2(qv.y, qv.y);
  }

  u64 myrw[8];
#pragma unroll
  for (int r = 0; r < 2; r++) {
#pragma unroll
    for (int p = 0; p < 4; p++) {
      int m0 = wq * 8 + 2 * p - (w1 + r) + 31;
      u64 z0 = 0ull, z1 = 0ull;
#pragma unroll
      for (int d = 0; d < 8; d++) {
        z0 = fma2(q2[r][d], relwd[m0 * 8 + d], z0);
        z1 = fma2(q2[r][d], relwd[(m0 + 1) * 8 + d], z1);
      }
      float alo, ahi, blo, bhi;
      unpack2(z0, alo, ahi); unpack2(z1, blo, bhi);
      myrw[r * 4 + p] = pack2(alo, blo);
    }
  }

  u64 acc2[2][8];
  u64 ssum2[2] = {0ull, 0ull};
#pragma unroll
  for (int d = 0; d < 8; d++) { acc2[0][d] = 0ull; acc2[1][d] = 0ull; }

#pragma unroll 1
  for (int hh = 0; hh < 32; hh++) {
    int h2 = (hh + wid * 8) & 31;     // per-warp phase stagger
    const u64* rhp = relhd + (h2 - h1 + 31) * 8;
    u64 rh0 = 0ull, rh1 = 0ull;
#pragma unroll
    for (int d = 0; d < 8; d++) {
      u64 rv = rhp[d];
      rh0 = fma2(q2[0][d], rv, rh0);
      rh1 = fma2(q2[1][d], rv, rh1);
    }

    u64 s[8];
#pragma unroll
    for (int p = 0; p < 4; p++) {
      s[p] = add2(myrw[p], rh0);
      s[4 + p] = add2(myrw[4 + p], rh1);
    }
    int base = h2 * 8;
#pragma unroll
    for (int d = 0; d < 8; d++) {
      ulonglong2 kkA = *(const ulonglong2*)(kpl + d * 256 + base);
      ulonglong2 kkB = *(const ulonglong2*)(kpl + d * 256 + base + 4);
      u64 qa = q2[0][d], qb2 = q2[1][d];
      s[0] = fma2(qa, kkA.x, s[0]); s[1] = fma2(qa, kkA.y, s[1]);
      s[2] = fma2(qa, kkB.x, s[2]); s[3] = fma2(qa, kkB.y, s[3]);
      s[4] = fma2(qb2, kkA.x, s[4]); s[5] = fma2(qb2, kkA.y, s[5]);
      s[6] = fma2(qb2, kkB.x, s[6]); s[7] = fma2(qb2, kkB.y, s[7]);
    }

    u64 pexp[8];
#pragma unroll
    for (int k = 0; k < 8; k++) {
      float lo, hi; unpack2(s[k], lo, hi);
      pexp[k] = pack2(ex2f(lo), ex2f(hi));
    }
    ssum2[0] = add2(ssum2[0], add2(add2(pexp[0], pexp[1]), add2(pexp[2], pexp[3])));
    ssum2[1] = add2(ssum2[1], add2(add2(pexp[4], pexp[5]), add2(pexp[6], pexp[7])));

#pragma unroll
    for (int d = 0; d < 8; d++) {
      ulonglong2 vvA = *(const ulonglong2*)(vpl + d * 256 + base);
      ulonglong2 vvB = *(const ulonglong2*)(vpl + d * 256 + base + 4);
      u64 a0 = acc2[0][d], a1 = acc2[1][d];
      a0 = fma2(pexp[0], vvA.x, a0); a0 = fma2(pexp[1], vvA.y, a0);
      a0 = fma2(pexp[2], vvB.x, a0); a0 = fma2(pexp[3], vvB.y, a0);
      a1 = fma2(pexp[4], vvA.x, a1); a1 = fma2(pexp[5], vvA.y, a1);
      a1 = fma2(pexp[6], vvB.x, a1); a1 = fma2(pexp[7], vvB.y, a1);
      acc2[0][d] = a0; acc2[1][d] = a1;
    }
  }

  float s0lo, s0hi, s1lo, s1hi;
  unpack2(ssum2[0], s0lo, s0hi);
  unpack2(ssum2[1], s1lo, s1hi);
  *(float2*)(pssum + ((wq * 8 + b) * 8 + n) * HW + i0) =
      make_float2(s0lo + s0hi, s1lo + s1hi);
  float* ab = pacc + ((wq * 8 + b) * 64 + n * 8) * HW + i0;
#pragma unroll
  for (int d = 0; d < 8; d++) {
    float a0, a1, b0, b1;
    unpack2(acc2[0][d], a0, a1);
    unpack2(acc2[1][d], b0, b1);
    *(float2*)(ab + d * HW) = make_float2(a0 + a1, b0 + b1);
  }
}

// ---------------------------------------------------------------------------
// Output projection (R12 tiling, float4-vectorized merges).
// grid (8 b, 2 og, 8 pt), block 256.
// ---------------------------------------------------------------------------
__global__ __launch_bounds__(256) void proj_kernel(
    const float* __restrict__ pacc, const float* __restrict__ pssum,
    const float* __restrict__ convp, const float* __restrict__ conv_b,
    const float* __restrict__ w, const float* __restrict__ bias,
    float* __restrict__ out) {
  extern __shared__ char smraw[];
  float* invs = (float*)smraw;                     // [8][128] 4KB
  float* xs = (float*)(smraw + 4096);              // [64][128] 32KB
  u64* ws2 = (u64*)(smraw + 4096 + 32768);         // [64][32] 16KB
  int b = blockIdx.x, og = blockIdx.y, pt = blockIdx.z;
  int t = threadIdx.x;
  int p0 = pt * 128;

  // pssum merge: float4 (256 float4 = 1024 floats)
  for (int i = t; i < 256; i += 256) {
    int n = i >> 5, pp4 = i & 31;
    int idx = (b * 8 + n) * HW + p0 + pp4 * 4;
    float4 a0 = *(const float4*)(pssum + idx);
    float4 a1 = *(const float4*)(pssum + idx + 64 * HW);
    float4 a2 = *(const float4*)(pssum + idx + 128 * HW);
    float4 a3 = *(const float4*)(pssum + idx + 192 * HW);
    float4 r;
    r.x = 1.f / (a0.x + a1.x + a2.x + a3.x);
    r.y = 1.f / (a0.y + a1.y + a2.y + a3.y);
    r.z = 1.f / (a0.z + a1.z + a2.z + a3.z);
    r.w = 1.f / (a0.w + a1.w + a2.w + a3.w);
    *(float4*)&invs[n * 128 + pp4 * 4] = r;
  }
  for (int i = t; i < 64 * 32; i += 256) {
    int c = i >> 5, o = i & 31;
    float wv = w[(og * 32 + o) * 64 + c];
    ws2[i] = pack2(wv, wv);
  }
  __syncthreads();
  // pacc merge + normalize: float4 (2048 float4 = 8192 floats)
  for (int i = t; i < 2048; i += 256) {
    int c = i >> 5, pp4 = i & 31;
    int idx = (b * 64 + c) * HW + p0 + pp4 * 4;
    float4 a0 = *(const float4*)(pacc + idx);
    float4 a1 = *(const float4*)(pacc + idx + 512 * HW);
    float4 a2 = *(const float4*)(pacc + idx + 1024 * HW);
    float4 a3 = *(const float4*)(pacc + idx + 1536 * HW);
    float4 iv = *(const float4*)&invs[(c >> 3) * 128 + pp4 * 4];
    float4 r;
    r.x = (a0.x + a1.x + a2.x + a3.x) * iv.x;
    r.y = (a0.y + a1.y + a2.y + a3.y) * iv.y;
    r.z = (a0.z + a1.z + a2.z + a3.z) * iv.z;
    r.w = (a0.w + a1.w + a2.w + a3.w) * iv.w;
    *(float4*)&xs[c * 128 + pp4 * 4] = r;
  }
  __syncthreads();

  int oi = t >> 5, pi = t & 31;
  u64 acc2[4][2];
#pragma unroll
  for (int a = 0; a < 4; a++) { acc2[a][0] = 0ull; acc2[a][1] = 0ull; }

  for (int c0 = 0; c0 < 64; c0 += 4) {
    u64 xv[4][2], wv[4][4];
#pragma unroll
    for (int cc = 0; cc < 4; cc++) {
      xv[cc][0] = *(const u64*)(xs + (c0 + cc) * 128 + pi * 2);
      xv[cc][1] = *(const u64*)(xs + (c0 + cc) * 128 + 64 + pi * 2);
    }
#pragma unroll
    for (int cc = 0; cc < 4; cc++)
#pragma unroll
      for (int a = 0; a < 4; a++) wv[cc][a] = ws2[(c0 + cc) * 32 + oi * 4 + a];
#pragma unroll
    for (int cc = 0; cc < 4; cc++)
#pragma unroll
      for (int a = 0; a < 4; a++) {
        acc2[a][0] = fma2(wv[cc][a], xv[cc][0], acc2[a][0]);
        acc2[a][1] = fma2(wv[cc][a], xv[cc][1], acc2[a][1]);
      }
  }

#pragma unroll
  for (int a = 0; a < 4; a++) {
    int o = og * 32 + oi * 4 + a;
    float bb = bias[o];
    float* ob = out + (b * 128 + 64 + o) * HW + p0;
#pragma unroll
    for (int k = 0; k < 2; k++) {
      float lo, hi; unpack2(acc2[a][k], lo, hi);
      *(float2*)(ob + 64 * k + pi * 2) = make_float2(lo + bb, hi + bb);
    }
  }

  // conv partial merge (og==0): float4
  if (og == 0) {
    for (int i = t; i < 2048; i += 256) {
      int oc = i >> 5, pp4 = i & 31;
      int idx = (b * 64 + oc) * HW + p0 + pp4 * 4;
      float4 a0 = *(const float4*)(convp + idx);
      float4 a1 = *(const float4*)(convp + idx + 512 * HW);
      float4 a2 = *(const float4*)(convp + idx + 1024 * HW);
      float4 a3 = *(const float4*)(convp + idx + 1536 * HW);
      float bb = conv_b[oc];
      float4 r;
      r.x = a0.x + a1.x + a2.x + a3.x + bb;
      r.y = a0.y + a1.y + a2.y + a3.y + bb;
      r.z = a0.z + a1.z + a2.z + a3.z + bb;
      r.w = a0.w + a1.w + a2.w + a3.w + bb;
      *(float4*)(out + (b * 128 + oc) * HW + p0 + pp4 * 4) = r;
    }
  }
}

// ---------------------------------------------------------------------------
extern "C" void kernel_launch(void* const* d_in, const int* in_sizes, int n_in,
                              void* d_out, int out_size) {
  (void)in_sizes; (void)n_in; (void)out_size;
  const float* x      = (const float*)d_in[0];
  const float* conv_w = (const float*)d_in[1];
  const float* conv_b = (const float*)d_in[2];
  const float* qkv_w  = (const float*)d_in[3];
  const float* qkv_b  = (const float*)d_in[4];
  const float* attn_w = (const float*)d_in[5];
  const float* attn_b = (const float*)d_in[6];
  const float* relw   = (const float*)d_in[7];
  const float* relh   = (const float*)d_in[8];
  float* out = (float*)d_out;

  float *qkv_s = nullptr, *convp = nullptr, *pacc = nullptr, *pssum = nullptr;
  cudaGetSymbolAddress((void**)&qkv_s, g_qkv);
  cudaGetSymbolAddress((void**)&convp, g_convp);
  cudaGetSymbolAddress((void**)&pacc, g_pacc);
  cudaGetSymbolAddress((void**)&pssum, g_pssum);

  const int PREP_SMEM = 49152;
  const int PROJ_SMEM = 4096 + 32768 + 16384;
  cudaFuncSetAttribute(prep_kernel, cudaFuncAttributeMaxDynamicSharedMemorySize, PREP_SMEM);
  cudaFuncSetAttribute(attn_kernel, cudaFuncAttributeMaxDynamicSharedMemorySize, AT5_SMEM);
  cudaFuncSetAttribute(proj_kernel, cudaFuncAttributeMaxDynamicSharedMemorySize, PROJ_SMEM);

  prep_kernel<<<896, 256, PREP_SMEM>>>(x, conv_w, qkv_w, qkv_b, convp, qkv_s);
  attn_kernel<<<dim3(64, 4, 4), 128, AT5_SMEM>>>(qkv_s, relw, relh, pacc, pssum);
  proj_kernel<<<dim3(8, 2, 8), 256, PROJ_SMEM>>>(pacc, pssum, convp, conv_b,
                                                 attn_w, attn_b, out);
}

// round 17
// speedup vs baseline: 1.7797x; 1.0133x over previous
#include <cuda_runtime.h>

#define HW 1024

// Scratch buffers
__device__ float g_qkv[8 * 192 * HW];        // [b][192][1024]; q pre-scaled by dkh^-0.5*log2e
__device__ float g_convp[4 * 8 * 64 * HW];   // [cs][b][64][1024] conv partial sums (no bias)
__device__ float g_pacc[4 * 8 * 64 * HW];    // [wq][b][64][1024] partial softmax-weighted V sums
__device__ float g_pssum[4 * 8 * 8 * HW];    // [wq][b][n][1024] partial exp sums

typedef unsigned long long u64;

__device__ __forceinline__ u64 fma2(u64 a, u64 b, u64 c) {
  u64 d; asm("fma.rn.f32x2 %0,%1,%2,%3;" : "=l"(d) : "l"(a), "l"(b), "l"(c)); return d;
}
__device__ __forceinline__ u64 add2(u64 a, u64 b) {
  u64 d; asm("add.rn.f32x2 %0,%1,%2;" : "=l"(d) : "l"(a), "l"(b)); return d;
}
__device__ __forceinline__ u64 pack2(float lo, float hi) {
  u64 d; asm("mov.b64 %0,{%1,%2};" : "=l"(d) : "f"(lo), "f"(hi)); return d;
}
__device__ __forceinline__ void unpack2(u64 v, float& lo, float& hi) {
  asm("mov.b64 {%0,%1},%2;" : "=f"(lo), "=f"(hi) : "l"(v));
}
__device__ __forceinline__ float ex2f(float x) {
  float y; asm("ex2.approx.ftz.f32 %0,%1;" : "=f"(y) : "f"(x)); return y;
}
__device__ __forceinline__ float4 ldcs4(const float* p) {
  return __ldcs((const float4*)p);
}

// ---------------------------------------------------------------------------
// Fused prep (unchanged from R16).
// blocks [0,512): conv3x3 c-split partials; blocks [512,896): qkv projection.
// ---------------------------------------------------------------------------
__global__ __launch_bounds__(256, 3) void prep_kernel(
    const float* __restrict__ x,
    const float* __restrict__ conv_w,
    const float* __restrict__ qkv_w, const float* __restrict__ qkv_b,
    float* __restrict__ convp, float* __restrict__ qkv_out) {
  extern __shared__ char smraw[];
  int blk = blockIdx.x;
  int t = threadIdx.x;

  if (blk < 512) {
    u64* wdup = (u64*)smraw;                 // [4 o][16 c][9] dup u64
    float* xs = (float*)(smraw + 4608);      // [8 cc][34][34] planar
    int cs = blk >> 7;
    int rem = blk & 127;
    int b = rem >> 4, og = rem & 15;
    int cbase = cs * 16;

    for (int i = t; i < 576; i += 256) {
      int o = i / 144, r2 = i - o * 144;
      float wv = conv_w[(og * 4 + o) * 576 + cbase * 9 + r2];
      wdup[i] = pack2(wv, wv);
    }
    for (int i = t; i < 9248; i += 256) xs[i] = 0.f;

    int xcol = t & 31, m0 = t >> 5;
    u64 acc[4][2];
#pragma unroll
    for (int o = 0; o < 4; o++) { acc[o][0] = 0ull; acc[o][1] = 0ull; }

    for (int chunk = 0; chunk < 2; chunk++) {
      __syncthreads();
#pragma unroll
      for (int cc = 0; cc < 8; cc++) {
        const float* xp = x + (b * 64 + cbase + chunk * 8 + cc) * HW;
#pragma unroll
        for (int rg = 0; rg < 4; rg++) {
          int row = rg * 8 + m0;
          xs[cc * 1156 + (row + 1) * 34 + xcol + 1] = xp[row * 32 + xcol];
        }
      }
      __syncthreads();

#pragma unroll
      for (int cc = 0; cc < 8; cc++) {
        const float* xc = xs + cc * 1156;
        int crel = chunk * 8 + cc;
        u64 pr[2][9];
#pragma unroll
        for (int pi = 0; pi < 2; pi++) {
          int m = m0 + pi * 8;
          const float* base = xc + (2 * m) * 34 + xcol;
#pragma unroll
          for (int kw = 0; kw < 3; kw++) {
            float s0 = base[kw], s1 = base[34 + kw];
            float s2 = base[68 + kw], s3 = base[102 + kw];
            pr[pi][0 + kw] = pack2(s0, s1);
            pr[pi][3 + kw] = pack2(s1, s2);
            pr[pi][6 + kw] = pack2(s2, s3);
          }
        }
        const u64* wc = wdup + crel * 9;
#pragma unroll
        for (int o = 0; o < 4; o++) {
          const u64* wo = wc + o * 144;
          u64 a0 = acc[o][0], a1 = acc[o][1];
#pragma unroll
          for (int k = 0; k < 9; k++) {
            u64 wk = wo[k];
            a0 = fma2(pr[0][k], wk, a0);
            a1 = fma2(pr[1][k], wk, a1);
          }
          acc[o][0] = a0; acc[o][1] = a1;
        }
      }
    }

    float* cpb = convp + (cs * 8 + b) * 64 * HW + og * 4 * HW;
#pragma unroll
    for (int o = 0; o < 4; o++) {
#pragma unroll
      for (int pi = 0; pi < 2; pi++) {
        int m = m0 + pi * 8;
        float lo, hi; unpack2(acc[o][pi], lo, hi);
        cpb[o * HW + (2 * m) * 32 + xcol] = lo;
        cpb[o * HW + (2 * m + 1) * 32 + xcol] = hi;
      }
    }
  } else {
    float* xs = (float*)smraw;               // [64][128] 32KB
    u64* ws2 = (u64*)(smraw + 32768);        // [64][32]  16KB
    int r = blk - 512;
    int b = r / 48;
    int rem = r - b * 48;
    int og = rem >> 3, pt = rem & 7;
    int p0 = pt * 128;

    for (int i = t; i < 2048; i += 256) {
      int c = i >> 5, pp4 = i & 31;
      *(float4*)&xs[c * 128 + pp4 * 4] =
          *(const float4*)&x[(b * 64 + c) * HW + p0 + pp4 * 4];
    }
    for (int i = t; i < 64 * 32; i += 256) {
      int c = i >> 5, o = i & 31;
      float wv = qkv_w[(og * 32 + o) * 64 + c];
      ws2[i] = pack2(wv, wv);
    }
    __syncthreads();

    int oi = t >> 5, pi = t & 31;
    u64 acc2[4][2];
#pragma unroll
    for (int a = 0; a < 4; a++) { acc2[a][0] = 0ull; acc2[a][1] = 0ull; }

    for (int c0 = 0; c0 < 64; c0 += 4) {
      u64 xv[4][2], wv[4][4];
#pragma unroll
      for (int cc = 0; cc < 4; cc++) {
        xv[cc][0] = *(const u64*)(xs + (c0 + cc) * 128 + pi * 2);
        xv[cc][1] = *(const u64*)(xs + (c0 + cc) * 128 + 64 + pi * 2);
      }
#pragma unroll
      for (int cc = 0; cc < 4; cc++)
#pragma unroll
        for (int a = 0; a < 4; a++) wv[cc][a] = ws2[(c0 + cc) * 32 + oi * 4 + a];
#pragma unroll
      for (int cc = 0; cc < 4; cc++)
#pragma unroll
        for (int a = 0; a < 4; a++) {
          acc2[a][0] = fma2(wv[cc][a], xv[cc][0], acc2[a][0]);
          acc2[a][1] = fma2(wv[cc][a], xv[cc][1], acc2[a][1]);
        }
    }

#pragma unroll
    for (int a = 0; a < 4; a++) {
      int o = og * 32 + oi * 4 + a;
      float bb = qkv_b[o];
      float sc = (o < 64) ? (0.35355339059327373f * 1.4426950408889634f) : 1.f;
      float* ob = qkv_out + (b * 192 + o) * HW + p0;
#pragma unroll
      for (int k = 0; k < 2; k++) {
        float lo, hi; unpack2(acc2[a][k], lo, hi);
        *(float2*)(ob + 64 * k + pi * 2) = make_float2(sc * (lo + bb), sc * (hi + bb));
      }
    }
  }
}

// ---------------------------------------------------------------------------
// Attention v5 (unchanged from R12/R16).
// ---------------------------------------------------------------------------
#define AT5_K    0                     // [8 d][256 jl] f32 = 8192
#define AT5_V    8192                  // 8192
#define AT5_RELW 16384                 // 504 u64 dup = 4032
#define AT5_RELH 20416                 // 4032
#define AT5_SMEM 24448

__global__ __launch_bounds__(128, 4) void attn_kernel(
    const float* __restrict__ qkv,
    const float* __restrict__ relw, const float* __restrict__ relh,
    float* __restrict__ pacc, float* __restrict__ pssum) {
  extern __shared__ char sm[];
  float* kpl = (float*)(sm + AT5_K);
  float* vpl = (float*)(sm + AT5_V);
  u64* relwd = (u64*)(sm + AT5_RELW);
  u64* relhd = (u64*)(sm + AT5_RELH);
  int t = threadIdx.x;
  int bn = blockIdx.x;
  int b = bn >> 3, n = bn & 7;
  int rowg = blockIdx.y;   // 0..3
  int wq = blockIdx.z;     // 0..3

  const float* qb = qkv + (b * 192 + n * 8) * HW;
  const float* kb = qkv + (b * 192 + 64 + n * 8) * HW;
  const float* vb = qkv + (b * 192 + 128 + n * 8) * HW;

  for (int e = t; e < 2048; e += 128) {
    int d = e >> 8, jl = e & 255;
    int j = (jl >> 3) * 32 + wq * 8 + (jl & 7);
    kpl[e] = kb[d * HW + j];
    vpl[e] = vb[d * HW + j];
  }
  for (int e = t; e < 504; e += 128) {
    float a = relw[e]; relwd[e] = pack2(a, a);
    float c = relh[e]; relhd[e] = pack2(c, c);
  }
  __syncthreads();

  int i0 = rowg * 256 + 2 * t;       // rows i0, i0+1 (same h1; w1 <= 30)
  int h1 = i0 >> 5, w1 = i0 & 31;
  int wid = t >> 5;                  // warp id 0..3 -> h2 phase offset

  u64 q2[2][8];
#pragma unroll
  for (int d = 0; d < 8; d++) {
    float2 qv = *(const float2*)(qb + d * HW + i0);
    q2[0][d] = pack2(qv.x, qv.x);
    q2[1][d] = pack2(qv.y, qv.y);
  }

  u64 myrw[8];
#pragma unroll
  for (int r = 0; r < 2; r++) {
#pragma unroll
    for (int p = 0; p < 4; p++) {
      int m0 = wq * 8 + 2 * p - (w1 + r) + 31;
      u64 z0 = 0ull, z1 = 0ull;
#pragma unroll
      for (int d = 0; d < 8; d++) {
        z0 = fma2(q2[r][d], relwd[m0 * 8 + d], z0);
        z1 = fma2(q2[r][d], relwd[(m0 + 1) * 8 + d], z1);
      }
      float alo, ahi, blo, bhi;
      unpack2(z0, alo, ahi); unpack2(z1, blo, bhi);
      myrw[r * 4 + p] = pack2(alo, blo);
    }
  }

  u64 acc2[2][8];
  u64 ssum2[2] = {0ull, 0ull};
#pragma unroll
  for (int d = 0; d < 8; d++) { acc2[0][d] = 0ull; acc2[1][d] = 0ull; }

#pragma unroll 1
  for (int hh = 0; hh < 32; hh++) {
    int h2 = (hh + wid * 8) & 31;     // per-warp phase stagger
    const u64* rhp = relhd + (h2 - h1 + 31) * 8;
    u64 rh0 = 0ull, rh1 = 0ull;
#pragma unroll
    for (int d = 0; d < 8; d++) {
      u64 rv = rhp[d];
      rh0 = fma2(q2[0][d], rv, rh0);
      rh1 = fma2(q2[1][d], rv, rh1);
    }

    u64 s[8];
#pragma unroll
    for (int p = 0; p < 4; p++) {
      s[p] = add2(myrw[p], rh0);
      s[4 + p] = add2(myrw[4 + p], rh1);
    }
    int base = h2 * 8;
#pragma unroll
    for (int d = 0; d < 8; d++) {
      ulonglong2 kkA = *(const ulonglong2*)(kpl + d * 256 + base);
      ulonglong2 kkB = *(const ulonglong2*)(kpl + d * 256 + base + 4);
      u64 qa = q2[0][d], qb2 = q2[1][d];
      s[0] = fma2(qa, kkA.x, s[0]); s[1] = fma2(qa, kkA.y, s[1]);
      s[2] = fma2(qa, kkB.x, s[2]); s[3] = fma2(qa, kkB.y, s[3]);
      s[4] = fma2(qb2, kkA.x, s[4]); s[5] = fma2(qb2, kkA.y, s[5]);
      s[6] = fma2(qb2, kkB.x, s[6]); s[7] = fma2(qb2, kkB.y, s[7]);
    }

    u64 pexp[8];
#pragma unroll
    for (int k = 0; k < 8; k++) {
      float lo, hi; unpack2(s[k], lo, hi);
      pexp[k] = pack2(ex2f(lo), ex2f(hi));
    }
    ssum2[0] = add2(ssum2[0], add2(add2(pexp[0], pexp[1]), add2(pexp[2], pexp[3])));
    ssum2[1] = add2(ssum2[1], add2(add2(pexp[4], pexp[5]), add2(pexp[6], pexp[7])));

#pragma unroll
    for (int d = 0; d < 8; d++) {
      ulonglong2 vvA = *(const ulonglong2*)(vpl + d * 256 + base);
      ulonglong2 vvB = *(const ulonglong2*)(vpl + d * 256 + base + 4);
      u64 a0 = acc2[0][d], a1 = acc2[1][d];
      a0 = fma2(pexp[0], vvA.x, a0); a0 = fma2(pexp[1], vvA.y, a0);
      a0 = fma2(pexp[2], vvB.x, a0); a0 = fma2(pexp[3], vvB.y, a0);
      a1 = fma2(pexp[4], vvA.x, a1); a1 = fma2(pexp[5], vvA.y, a1);
      a1 = fma2(pexp[6], vvB.x, a1); a1 = fma2(pexp[7], vvB.y, a1);
      acc2[0][d] = a0; acc2[1][d] = a1;
    }
  }

  float s0lo, s0hi, s1lo, s1hi;
  unpack2(ssum2[0], s0lo, s0hi);
  unpack2(ssum2[1], s1lo, s1hi);
  *(float2*)(pssum + ((wq * 8 + b) * 8 + n) * HW + i0) =
      make_float2(s0lo + s0hi, s1lo + s1hi);
  float* ab = pacc + ((wq * 8 + b) * 64 + n * 8) * HW + i0;
#pragma unroll
  for (int d = 0; d < 8; d++) {
    float a0, a1, b0, b1;
    unpack2(acc2[0][d], a0, a1);
    unpack2(acc2[1][d], b0, b1);
    *(float2*)(ab + d * HW) = make_float2(a0 + a1, b0 + b1);
  }
}

// ---------------------------------------------------------------------------
// Output projection v3: float4 + __ldcs streaming merges; conv merge split
// between og==0 (ch 0..31) and og==1 (ch 32..63) to balance blocks.
// grid (8 b, 2 og, 8 pt), block 256.
// ---------------------------------------------------------------------------
__global__ __launch_bounds__(256) void proj_kernel(
    const float* __restrict__ pacc, const float* __restrict__ pssum,
    const float* __restrict__ convp, const float* __restrict__ conv_b,
    const float* __restrict__ w, const float* __restrict__ bias,
    float* __restrict__ out) {
  extern __shared__ char smraw[];
  float* invs = (float*)smraw;                     // [8][128] 4KB
  float* xs = (float*)(smraw + 4096);              // [64][128] 32KB
  u64* ws2 = (u64*)(smraw + 4096 + 32768);         // [64][32] 16KB
  int b = blockIdx.x, og = blockIdx.y, pt = blockIdx.z;
  int t = threadIdx.x;
  int p0 = pt * 128;

  // pssum merge: float4 streaming
  for (int i = t; i < 256; i += 256) {
    int n = i >> 5, pp4 = i & 31;
    int idx = (b * 8 + n) * HW + p0 + pp4 * 4;
    float4 a0 = ldcs4(pssum + idx);
    float4 a1 = ldcs4(pssum + idx + 64 * HW);
    float4 a2 = ldcs4(pssum + idx + 128 * HW);
    float4 a3 = ldcs4(pssum + idx + 192 * HW);
    float4 r;
    r.x = 1.f / (a0.x + a1.x + a2.x + a3.x);
    r.y = 1.f / (a0.y + a1.y + a2.y + a3.y);
    r.z = 1.f / (a0.z + a1.z + a2.z + a3.z);
    r.w = 1.f / (a0.w + a1.w + a2.w + a3.w);
    *(float4*)&invs[n * 128 + pp4 * 4] = r;
  }
  for (int i = t; i < 64 * 32; i += 256) {
    int c = i >> 5, o = i & 31;
    float wv = w[(og * 32 + o) * 64 + c];
    ws2[i] = pack2(wv, wv);
  }
  __syncthreads();
  // pacc merge + normalize: float4 streaming
  for (int i = t; i < 2048; i += 256) {
    int c = i >> 5, pp4 = i & 31;
    int idx = (b * 64 + c) * HW + p0 + pp4 * 4;
    float4 a0 = ldcs4(pacc + idx);
    float4 a1 = ldcs4(pacc + idx + 512 * HW);
    float4 a2 = ldcs4(pacc + idx + 1024 * HW);
    float4 a3 = ldcs4(pacc + idx + 1536 * HW);
    float4 iv = *(const float4*)&invs[(c >> 3) * 128 + pp4 * 4];
    float4 r;
    r.x = (a0.x + a1.x + a2.x + a3.x) * iv.x;
    r.y = (a0.y + a1.y + a2.y + a3.y) * iv.y;
    r.z = (a0.z + a1.z + a2.z + a3.z) * iv.z;
    r.w = (a0.w + a1.w + a2.w + a3.w) * iv.w;
    *(float4*)&xs[c * 128 + pp4 * 4] = r;
  }
  __syncthreads();

  int oi = t >> 5, pi = t & 31;
  u64 acc2[4][2];
#pragma unroll
  for (int a = 0; a < 4; a++) { acc2[a][0] = 0ull; acc2[a][1] = 0ull; }

  for (int c0 = 0; c0 < 64; c0 += 4) {
    u64 xv[4][2], wv[4][4];
#pragma unroll
    for (int cc = 0; cc < 4; cc++) {
      xv[cc][0] = *(const u64*)(xs + (c0 + cc) * 128 + pi * 2);
      xv[cc][1] = *(const u64*)(xs + (c0 + cc) * 128 + 64 + pi * 2);
    }
#pragma unroll
    for (int cc = 0; cc < 4; cc++)
#pragma unroll
      for (int a = 0; a < 4; a++) wv[cc][a] = ws2[(c0 + cc) * 32 + oi * 4 + a];
#pragma unroll
    for (int cc = 0; cc < 4; cc++)
#pragma unroll
      for (int a = 0; a < 4; a++) {
        acc2[a][0] = fma2(wv[cc][a], xv[cc][0], acc2[a][0]);
        acc2[a][1] = fma2(wv[cc][a], xv[cc][1], acc2[a][1]);
      }
  }

#pragma unroll
  for (int a = 0; a < 4; a++) {
    int o = og * 32 + oi * 4 + a;
    float bb = bias[o];
    float* ob = out + (b * 128 + 64 + o) * HW + p0;
#pragma unroll
    for (int k = 0; k < 2; k++) {
      float lo, hi; unpack2(acc2[a][k], lo, hi);
      *(float2*)(ob + 64 * k + pi * 2) = make_float2(lo + bb, hi + bb);
    }
  }

  // conv partial merge split across og: og==0 -> ch 0..31, og==1 -> ch 32..63
  {
    int ocbase = og * 32;
    for (int i = t; i < 1024; i += 256) {
      int oc = ocbase + (i >> 5), pp4 = i & 31;
      int idx = (b * 64 + oc) * HW + p0 + pp4 * 4;
      float4 a0 = ldcs4(convp + idx);
      float4 a1 = ldcs4(convp + idx + 512 * HW);
      float4 a2 = ldcs4(convp + idx + 1024 * HW);
      float4 a3 = ldcs4(convp + idx + 1536 * HW);
      float bb = conv_b[oc];
      float4 r;
      r.x = a0.x + a1.x + a2.x + a3.x + bb;
      r.y = a0.y + a1.y + a2.y + a3.y + bb;
      r.z = a0.z + a1.z + a2.z + a3.z + bb;
      r.w = a0.w + a1.w + a2.w + a3.w + bb;
      *(float4*)(out + (b * 128 + oc) * HW + p0 + pp4 * 4) = r;
    }
  }
}

// ---------------------------------------------------------------------------
extern "C" void kernel_launch(void* const* d_in, const int* in_sizes, int n_in,
                              void* d_out, int out_size) {
  (void)in_sizes; (void)n_in; (void)out_size;
  const float* x      = (const float*)d_in[0];
  const float* conv_w = (const float*)d_in[1];
  const float* conv_b = (const float*)d_in[2];
  const float* qkv_w  = (const float*)d_in[3];
  const float* qkv_b  = (const float*)d_in[4];
  const float* attn_w = (const float*)d_in[5];
  const float* attn_b = (const float*)d_in[6];
  const float* relw   = (const float*)d_in[7];
  const float* relh   = (const float*)d_in[8];
  float* out = (float*)d_out;

  float *qkv_s = nullptr, *convp = nullptr, *pacc = nullptr, *pssum = nullptr;
  cudaGetSymbolAddress((void**)&qkv_s, g_qkv);
  cudaGetSymbolAddress((void**)&convp, g_convp);
  cudaGetSymbolAddress((void**)&pacc, g_pacc);
  cudaGetSymbolAddress((void**)&pssum, g_pssum);

  const int PREP_SMEM = 49152;
  const int PROJ_SMEM = 4096 + 32768 + 16384;
  cudaFuncSetAttribute(prep_kernel, cudaFuncAttributeMaxDynamicSharedMemorySize, PREP_SMEM);
  cudaFuncSetAttribute(attn_kernel, cudaFuncAttributeMaxDynamicSharedMemorySize, AT5_SMEM);
  cudaFuncSetAttribute(proj_kernel, cudaFuncAttributeMaxDynamicSharedMemorySize, PROJ_SMEM);

  prep_kernel<<<896, 256, PREP_SMEM>>>(x, conv_w, qkv_w, qkv_b, convp, qkv_s);
  attn_kernel<<<dim3(64, 4, 4), 128, AT5_SMEM>>>(qkv_s, relw, relh, pacc, pssum);
  proj_kernel<<<dim3(8, 2, 8), 256, PROJ_SMEM>>>(pacc, pssum, convp, conv_b,
                                                 attn_w, attn_b, out);
}